// round 15
// baseline (speedup 1.0000x reference)
#include <cuda_runtime.h>
#include <cuda_bf16.h>
#include <cstdint>

#define BATCH 2
#define SEQ   2048
#define HDIM  768
#define IDIM  256
#define MTOK  (BATCH * SEQ)   // 4096 tokens

// ---------------------------------------------------------------------------
// Scratch (device globals; no allocation allowed)
// ---------------------------------------------------------------------------
__device__ unsigned g_xtf [MTOK * HDIM];
__device__ unsigned g_qwtf[HDIM * HDIM];
__device__ unsigned g_kwtf[HDIM * HDIM];
__device__ unsigned g_vwtf[HDIM * HDIM];
__device__ unsigned g_owtf[HDIM * HDIM];
__device__ unsigned g_spwtf [IDIM * HDIM];
__device__ unsigned g_saiwtf[3 * IDIM * IDIM];
__device__ unsigned g_saowtf[IDIM * IDIM];

__device__ unsigned g_Q[MTOK * HDIM];
__device__ unsigned g_K[MTOK * HDIM];
__device__ unsigned g_V[MTOK * HDIM];
__device__ unsigned g_attn[MTOK * HDIM];
__device__ unsigned g_h0[MTOK * IDIM];
__device__ unsigned g_qkvs[MTOK * 3 * IDIM];
__device__ unsigned g_sattn[MTOK * IDIM];
__device__ float    g_h1[MTOK * IDIM];
__device__ float    g_biasS[MTOK];
__device__ float    g_biasM[MTOK];

// transposed V: VT[b][h][d][S] (tf32 bits)
__device__ unsigned g_VTm[BATCH * 12 * 64 * SEQ];
__device__ unsigned g_VTs[BATCH * 4 * 64 * SEQ];

// ---------------------------------------------------------------------------
// Helpers
// ---------------------------------------------------------------------------
__device__ __forceinline__ unsigned f2tf(float f) {
    unsigned r; asm("cvt.rna.tf32.f32 %0, %1;" : "=r"(r) : "f"(f)); return r;
}
__device__ __forceinline__ float ex2(float x) {
    float r; asm("ex2.approx.f32 %0, %1;" : "=f"(r) : "f"(x)); return r;
}
__device__ __forceinline__ void mma8(float c[4], const unsigned a[4], const unsigned b[2]) {
    asm volatile(
        "mma.sync.aligned.m16n8k8.row.col.f32.tf32.tf32.f32 "
        "{%0,%1,%2,%3},{%4,%5,%6,%7},{%8,%9},{%0,%1,%2,%3};"
        : "+f"(c[0]), "+f"(c[1]), "+f"(c[2]), "+f"(c[3])
        : "r"(a[0]), "r"(a[1]), "r"(a[2]), "r"(a[3]), "r"(b[0]), "r"(b[1]));
}
__device__ __forceinline__ void ldmx4(unsigned& r0, unsigned& r1, unsigned& r2, unsigned& r3,
                                      unsigned addr) {
    asm volatile("ldmatrix.sync.aligned.m8n8.x4.shared.b16 {%0,%1,%2,%3}, [%4];"
                 : "=r"(r0), "=r"(r1), "=r"(r2), "=r"(r3) : "r"(addr));
}
__device__ __forceinline__ unsigned s2u(const void* p) {
    return (unsigned)__cvta_generic_to_shared(p);
}
__device__ __forceinline__ void cp16(unsigned dst, const void* src) {
    asm volatile("cp.async.ca.shared.global [%0], [%1], 16;" :: "r"(dst), "l"(src));
}
__device__ __forceinline__ void cp_commit() { asm volatile("cp.async.commit_group;"); }
__device__ __forceinline__ void cp_wait0() { asm volatile("cp.async.wait_group 0;"); }
__device__ __forceinline__ void cp_wait1() { asm volatile("cp.async.wait_group 1;"); }
__device__ __forceinline__ void cp_wait2() { asm volatile("cp.async.wait_group 2;"); }

// ---------------------------------------------------------------------------
// One-shot tf32 conversion of x + all GEMM weights + mask bias (9 segments)
// ---------------------------------------------------------------------------
__global__ __launch_bounds__(256) void cvt_tf32_all(
    const float* __restrict__ x,   const float* __restrict__ qw,
    const float* __restrict__ kw,  const float* __restrict__ vw,
    const float* __restrict__ ow,  const float* __restrict__ spw,
    const float* __restrict__ saiw,const float* __restrict__ saow,
    const int* __restrict__ mask,
    unsigned* __restrict__ xo,  unsigned* __restrict__ qo,
    unsigned* __restrict__ ko,  unsigned* __restrict__ vo,
    unsigned* __restrict__ oo,  unsigned* __restrict__ spo,
    unsigned* __restrict__ saio,unsigned* __restrict__ saoo,
    float* __restrict__ biasS)
{
    const int seg = blockIdx.y;
    if (seg == 8) {
        for (int i = blockIdx.x * 256 + threadIdx.x; i < MTOK; i += gridDim.x * 256)
            biasS[i] = (mask[i] > 0) ? 0.f : -1e9f;
        return;
    }
    int n;
    const float* s; unsigned* d;
    switch (seg) {
        case 0: s = x;    d = xo;   n = MTOK * HDIM;     break;
        case 1: s = qw;   d = qo;   n = HDIM * HDIM;     break;
        case 2: s = kw;   d = ko;   n = HDIM * HDIM;     break;
        case 3: s = vw;   d = vo;   n = HDIM * HDIM;     break;
        case 4: s = ow;   d = oo;   n = HDIM * HDIM;     break;
        case 5: s = spw;  d = spo;  n = IDIM * HDIM;     break;
        case 6: s = saiw; d = saio; n = 3 * IDIM * IDIM; break;
        default:s = saow; d = saoo; n = IDIM * IDIM;     break;
    }
    int n4 = n >> 2;
    for (int i = blockIdx.x * 256 + threadIdx.x; i < n4; i += gridDim.x * 256) {
        float4 v = ((const float4*)s)[i];
        ((uint4*)d)[i] = make_uint4(f2tf(v.x), f2tf(v.y), f2tf(v.z), f2tf(v.w));
    }
}

// ---------------------------------------------------------------------------
// V transpose: V[(b*S+key)*ld + v_off + h*64 + d] -> VT[((b*nh+h)*64+d)*S + key]
// ---------------------------------------------------------------------------
__global__ __launch_bounds__(256) void transpose_vt(
    const unsigned* __restrict__ V, unsigned* __restrict__ VT,
    int S, int ld, int v_off, int nh)
{
    __shared__ unsigned tsm[64 * 68];
    int b = blockIdx.z, h = blockIdx.y, k0 = blockIdx.x * 64;
    int tid = threadIdx.x;
    const unsigned* src = V + v_off + h * 64;

    #pragma unroll
    for (int i = 0; i < 4; i++) {
        int idx = tid + i * 256;
        int key = idx >> 4, d4 = (idx & 15) * 4;
        uint4 v = *(const uint4*)(src + (size_t)(b * S + k0 + key) * ld + d4);
        *(uint4*)&tsm[key * 68 + d4] = v;
    }
    __syncthreads();
    #pragma unroll
    for (int i = 0; i < 4; i++) {
        int idx = tid + i * 256;
        int d = idx >> 4, kk = (idx & 15) * 4;
        uint4 w = make_uint4(tsm[(kk + 0) * 68 + d], tsm[(kk + 1) * 68 + d],
                             tsm[(kk + 2) * 68 + d], tsm[(kk + 3) * 68 + d]);
        *(uint4*)(VT + ((size_t)(b * nh + h) * 64 + d) * S + k0 + kk) = w;
    }
}

// ---------------------------------------------------------------------------
// GEMM (tf32-bit inputs), BM x 128 tile, BK=32, cp.async 3-stage pipeline.
// ---------------------------------------------------------------------------
template<int BM, bool TF32OUT>
__device__ __forceinline__ void gemm_body(
    const unsigned* __restrict__ A, const unsigned* __restrict__ W,
    const float* __restrict__ bias, void* __restrict__ Cv,
    int M, int N, int K, unsigned* smemu)
{
    constexpr int MFRAG = BM / 32;
    constexpr int STG = (BM + 128) * 36;       // u32 per stage
    unsigned* As = smemu;                      // [3][BM*36] interleaved per stage
    // per-stage layout: A at stage*STG, B at stage*STG + BM*36

    int tid = threadIdx.x, warp = tid >> 5, lane = tid & 31, g = lane >> 2, tig = lane & 3;
    int wm = (warp & 1) * (BM / 2), wn = (warp >> 1) * 32;
    int bm = blockIdx.y * BM, bn = blockIdx.x * 128;

    float acc[MFRAG][4][4];
    #pragma unroll
    for (int mt = 0; mt < MFRAG; mt++)
        #pragma unroll
        for (int nt = 0; nt < 4; nt++)
            #pragma unroll
            for (int i = 0; i < 4; i++) acc[mt][nt][i] = 0.f;

    auto issue = [&](int stage, int k0) {
        unsigned* as = As + stage * STG;
        unsigned* bs = as + BM * 36;
        #pragma unroll
        for (int i = 0; i < BM / 32; i++) {
            int idx = tid + i * 256;
            int r = idx >> 3, c4 = (idx & 7) * 4;
            cp16(s2u(&as[r * 36 + c4]), A + (size_t)(bm + r) * K + k0 + c4);
        }
        #pragma unroll
        for (int i = 0; i < 4; i++) {
            int idx = tid + i * 256;
            int r = idx >> 3, c4 = (idx & 7) * 4;
            cp16(s2u(&bs[r * 36 + c4]), W + (size_t)(bn + r) * K + k0 + c4);
        }
        cp_commit();
    };

    int ntiles = K / 32;
    issue(0, 0);
    if (ntiles > 1) issue(1, 32);
    int stage = 0;
    for (int t = 0; t < ntiles; t++) {
        if (t + 2 < ntiles) { issue((stage + 2) % 3, (t + 2) * 32); cp_wait2(); }
        else if (t + 1 < ntiles) cp_wait1();
        else cp_wait0();
        __syncthreads();

        const unsigned* as = As + stage * STG;
        const unsigned* bs = as + BM * 36;
        #pragma unroll
        for (int ks = 0; ks < 4; ks++) {
            unsigned af[MFRAG][4], bf[4][2];
            #pragma unroll
            for (int mt = 0; mt < MFRAG; mt++) {
                int r0 = wm + mt * 16 + g;
                af[mt][0] = as[r0 * 36 + ks * 8 + tig];
                af[mt][1] = as[(r0 + 8) * 36 + ks * 8 + tig];
                af[mt][2] = as[r0 * 36 + ks * 8 + tig + 4];
                af[mt][3] = as[(r0 + 8) * 36 + ks * 8 + tig + 4];
            }
            #pragma unroll
            for (int nt = 0; nt < 4; nt++) {
                int r0 = wn + nt * 8 + g;
                bf[nt][0] = bs[r0 * 36 + ks * 8 + tig];
                bf[nt][1] = bs[r0 * 36 + ks * 8 + tig + 4];
            }
            #pragma unroll
            for (int mt = 0; mt < MFRAG; mt++)
                #pragma unroll
                for (int nt = 0; nt < 4; nt++)
                    mma8(acc[mt][nt], af[mt], bf[nt]);
        }
        __syncthreads();
        stage = (stage + 1) % 3;
    }

    #pragma unroll
    for (int mt = 0; mt < MFRAG; mt++) {
        int row0 = bm + wm + mt * 16 + g;
        #pragma unroll
        for (int nt = 0; nt < 4; nt++) {
            int col = bn + wn + nt * 8 + 2 * tig;
            float b0 = __ldg(bias + col), b1 = __ldg(bias + col + 1);
            float v00 = acc[mt][nt][0] + b0, v01 = acc[mt][nt][1] + b1;
            float v10 = acc[mt][nt][2] + b0, v11 = acc[mt][nt][3] + b1;
            if (TF32OUT) {
                unsigned* Cu = (unsigned*)Cv;
                *(uint2*)(Cu + (size_t)row0 * N + col) = make_uint2(f2tf(v00), f2tf(v01));
                *(uint2*)(Cu + (size_t)(row0 + 8) * N + col) = make_uint2(f2tf(v10), f2tf(v11));
            } else {
                float* C = (float*)Cv;
                *(float2*)(C + (size_t)row0 * N + col) = make_float2(v00, v01);
                *(float2*)(C + (size_t)(row0 + 8) * N + col) = make_float2(v10, v11);
            }
        }
    }
}

template<int BM, bool TF32OUT>
__global__ __launch_bounds__(256, 2) void gemm_u(
    const unsigned* __restrict__ A, const unsigned* __restrict__ W,
    const float* __restrict__ bias, void* __restrict__ C,
    int M, int N, int K)
{
    extern __shared__ unsigned smemu[];
    gemm_body<BM, TF32OUT>(A, W, bias, C, M, N, K, smemu);
}

__global__ __launch_bounds__(256, 2) void gemm_u_qkv(
    const unsigned* __restrict__ A,
    const unsigned* __restrict__ w0, const unsigned* __restrict__ w1, const unsigned* __restrict__ w2,
    const float* __restrict__ b0, const float* __restrict__ b1, const float* __restrict__ b2,
    unsigned* __restrict__ c0, unsigned* __restrict__ c1, unsigned* __restrict__ c2,
    int M, int N, int K)
{
    extern __shared__ unsigned smemu[];
    int z = blockIdx.z;
    const unsigned* W = (z == 0) ? w0 : (z == 1) ? w1 : w2;
    const float* bias = (z == 0) ? b0 : (z == 1) ? b1 : b2;
    unsigned* C = (z == 0) ? c0 : (z == 1) ? c1 : c2;
    gemm_body<128, true>(A, W, bias, C, M, N, K, smemu);
}

// ---------------------------------------------------------------------------
// Flash attention v8 (proven R14): tf32-bit Q/K + transposed V (VT[d][S]).
// ldmatrix fragment loads for K (QK), P and VT (PV). 256 thr / 128 queries.
// ---------------------------------------------------------------------------
template<bool TF32OUT>
__global__ __launch_bounds__(256, 2) void attn8(
    const unsigned* __restrict__ Qp, const unsigned* __restrict__ Kp,
    const unsigned* __restrict__ VT, const float* __restrict__ bias,
    void* __restrict__ Opv,
    int S, int ld, int q_off, int k_off, int nh, int o_ld, int o_off)
{
    extern __shared__ unsigned smu[];
    unsigned* KVs = smu;                       // [2][8704]: K rows 0-63, VT rows 64-127
    unsigned* Ps  = smu + 2 * 8704;            // [8704]
    float* bsL    = (float*)(smu + 3 * 8704);  // [2][64]

    const float LOG2E = 1.4426950408889634f;
    int b = blockIdx.z, h = blockIdx.y, q0 = blockIdx.x * 128;
    int tid = threadIdx.x, warp = tid >> 5, lane = tid & 31, g = lane >> 2, tig = lane & 3;

    const unsigned* qbase = Qp + q_off + h * 64;
    const unsigned* kbase = Kp + k_off + h * 64;
    const unsigned* vtb   = VT + (size_t)(b * nh + h) * 64 * S;

    // ---- stage Q (128x64 tf32) via cp.async ----
    #pragma unroll
    for (int i = 0; i < 8; i++) {
        int idx = tid + i * 256; int r = idx >> 4, s = (idx & 15) * 4;
        cp16(s2u(&Ps[r * 68 + s]), qbase + (size_t)(b * S + q0 + r) * ld + s);
    }
    cp_commit();

    auto issue = [&](int st, int kt) {
        #pragma unroll
        for (int i = 0; i < 4; i++) {
            int idx = tid + i * 256;
            int r = idx >> 4, c = (idx & 15) * 4;
            cp16(s2u(&KVs[st * 8704 + r * 68 + c]),
                 kbase + (size_t)(b * S + kt + r) * ld + c);
            cp16(s2u(&KVs[st * 8704 + (64 + r) * 68 + c]),
                 vtb + (size_t)r * S + kt + c);
        }
        if (tid < 16)
            cp16(s2u(&bsL[st * 64 + tid * 4]), bias + (size_t)b * S + kt + tid * 4);
        cp_commit();
    };

    issue(0, 0);
    cp_wait1();           // Q group retired
    __syncthreads();

    unsigned qf[8][4];
    int qr = warp * 16;
    #pragma unroll
    for (int ks = 0; ks < 8; ks++) {
        qf[ks][0] = Ps[(qr + g) * 68 + ks * 8 + tig];
        qf[ks][1] = Ps[(qr + g + 8) * 68 + ks * 8 + tig];
        qf[ks][2] = Ps[(qr + g) * 68 + ks * 8 + tig + 4];
        qf[ks][3] = Ps[(qr + g + 8) * 68 + ks * 8 + tig + 4];
    }

    float o[8][4];
    #pragma unroll
    for (int nt = 0; nt < 8; nt++)
        #pragma unroll
        for (int i = 0; i < 4; i++) o[nt][i] = 0.f;
    float m0 = -1e30f, m1 = -1e30f, l0 = 0.f, l1 = 0.f;
    const float sc = 0.125f * LOG2E;
    unsigned* pw = Ps + warp * 16 * 68;

    int lr8 = lane & 7, sel = lane >> 3;
    int koff = lr8 * 68 + ((sel & 1) ? 4 : 0) + ((sel >> 1) ? 8 * 68 : 0);
    int poff = lr8 * 68 + ((sel & 1) ? 8 * 68 : 0) + ((sel >> 1) ? 4 : 0);

    int ntile = S / 64;
    for (int t = 0; t < ntile; t++) {
        int st = t & 1;
        if (t + 1 < ntile) { issue(st ^ 1, (t + 1) * 64); cp_wait1(); }
        else               { cp_wait0(); }
        __syncthreads();

        const unsigned* KVf = KVs + st * 8704;
        const float* bsf = bsL + st * 64;

        // ---- S = Q K^T (ldmatrix K fragments) ----
        float sa[8][4];
        #pragma unroll
        for (int nt = 0; nt < 8; nt++)
            #pragma unroll
            for (int i = 0; i < 4; i++) sa[nt][i] = 0.f;
        #pragma unroll
        for (int ks = 0; ks < 8; ks++) {
            unsigned bf[8][2];
            #pragma unroll
            for (int ntp = 0; ntp < 4; ntp++) {
                unsigned addr = s2u(&KVf[ntp * 16 * 68 + ks * 8 + koff]);
                ldmx4(bf[2 * ntp][0], bf[2 * ntp][1],
                      bf[2 * ntp + 1][0], bf[2 * ntp + 1][1], addr);
            }
            #pragma unroll
            for (int nt = 0; nt < 8; nt++) mma8(sa[nt], qf[ks], bf[nt]);
        }

        // ---- online softmax (exp2 domain) ----
        float rm0 = -1e30f, rm1 = -1e30f;
        #pragma unroll
        for (int nt = 0; nt < 8; nt++) {
            float bl0 = bsf[nt * 8 + 2 * tig] * LOG2E;
            float bl1 = bsf[nt * 8 + 2 * tig + 1] * LOG2E;
            sa[nt][0] = sa[nt][0] * sc + bl0;
            sa[nt][1] = sa[nt][1] * sc + bl1;
            sa[nt][2] = sa[nt][2] * sc + bl0;
            sa[nt][3] = sa[nt][3] * sc + bl1;
            rm0 = fmaxf(rm0, fmaxf(sa[nt][0], sa[nt][1]));
            rm1 = fmaxf(rm1, fmaxf(sa[nt][2], sa[nt][3]));
        }
        rm0 = fmaxf(rm0, __shfl_xor_sync(0xffffffffu, rm0, 1));
        rm0 = fmaxf(rm0, __shfl_xor_sync(0xffffffffu, rm0, 2));
        rm1 = fmaxf(rm1, __shfl_xor_sync(0xffffffffu, rm1, 1));
        rm1 = fmaxf(rm1, __shfl_xor_sync(0xffffffffu, rm1, 2));
        float mn0 = fmaxf(m0, rm0), mn1 = fmaxf(m1, rm1);
        float c0 = ex2(m0 - mn0), c1 = ex2(m1 - mn1);
        float rs0 = 0.f, rs1 = 0.f;
        #pragma unroll
        for (int nt = 0; nt < 8; nt++) {
            sa[nt][0] = ex2(sa[nt][0] - mn0);
            sa[nt][1] = ex2(sa[nt][1] - mn0);
            sa[nt][2] = ex2(sa[nt][2] - mn1);
            sa[nt][3] = ex2(sa[nt][3] - mn1);
            rs0 += sa[nt][0] + sa[nt][1];
            rs1 += sa[nt][2] + sa[nt][3];
        }
        rs0 += __shfl_xor_sync(0xffffffffu, rs0, 1);
        rs0 += __shfl_xor_sync(0xffffffffu, rs0, 2);
        rs1 += __shfl_xor_sync(0xffffffffu, rs1, 1);
        rs1 += __shfl_xor_sync(0xffffffffu, rs1, 2);
        l0 = l0 * c0 + rs0; l1 = l1 * c1 + rs1;
        m0 = mn0; m1 = mn1;
        #pragma unroll
        for (int nt = 0; nt < 8; nt++) {
            o[nt][0] *= c0; o[nt][1] *= c0; o[nt][2] *= c1; o[nt][3] *= c1;
        }

        // ---- P -> warp-private smem (tf32) ----
        #pragma unroll
        for (int nt = 0; nt < 8; nt++) {
            int cc = nt * 8 + 2 * tig;
            pw[g * 68 + cc]           = f2tf(sa[nt][0]);
            pw[g * 68 + cc + 1]       = f2tf(sa[nt][1]);
            pw[(g + 8) * 68 + cc]     = f2tf(sa[nt][2]);
            pw[(g + 8) * 68 + cc + 1] = f2tf(sa[nt][3]);
        }
        __syncwarp();

        // ---- O += P V (ldmatrix P + ldmatrix VT fragments) ----
        #pragma unroll
        for (int ks = 0; ks < 8; ks++) {
            unsigned af[4];
            {
                unsigned addr = s2u(&pw[ks * 8 + poff]);
                ldmx4(af[0], af[1], af[2], af[3], addr);
            }
            unsigned bf2[8][2];
            #pragma unroll
            for (int ntp = 0; ntp < 4; ntp++) {
                unsigned addr = s2u(&KVf[64 * 68 + ntp * 16 * 68 + ks * 8 + koff]);
                ldmx4(bf2[2 * ntp][0], bf2[2 * ntp][1],
                      bf2[2 * ntp + 1][0], bf2[2 * ntp + 1][1], addr);
            }
            #pragma unroll
            for (int nt = 0; nt < 8; nt++) mma8(o[nt], af, bf2[nt]);
        }
        __syncthreads();
    }

    // ---- normalize + write ----
    float inv0 = 1.f / l0, inv1 = 1.f / l1;
    int row0 = b * S + q0 + warp * 16 + g;
    if (TF32OUT) {
        unsigned* ou0 = (unsigned*)Opv + o_off + h * 64 + (size_t)row0 * o_ld;
        unsigned* ou1 = (unsigned*)Opv + o_off + h * 64 + (size_t)(row0 + 8) * o_ld;
        #pragma unroll
        for (int nt = 0; nt < 8; nt++) {
            int col = nt * 8 + 2 * tig;
            *(uint2*)(ou0 + col) = make_uint2(f2tf(o[nt][0] * inv0), f2tf(o[nt][1] * inv0));
            *(uint2*)(ou1 + col) = make_uint2(f2tf(o[nt][2] * inv1), f2tf(o[nt][3] * inv1));
        }
    } else {
        float* ob0 = (float*)Opv + o_off + h * 64 + (size_t)row0 * o_ld;
        float* ob1 = (float*)Opv + o_off + h * 64 + (size_t)(row0 + 8) * o_ld;
        #pragma unroll
        for (int nt = 0; nt < 8; nt++) {
            int col = nt * 8 + 2 * tig;
            *(float2*)(ob0 + col) = make_float2(o[nt][0] * inv0, o[nt][1] * inv0);
            *(float2*)(ob1 + col) = make_float2(o[nt][2] * inv1, o[nt][3] * inv1);
        }
    }
}

// ---------------------------------------------------------------------------
// Fused survival MLPs, 8 tokens per block
// ---------------------------------------------------------------------------
__global__ __launch_bounds__(128) void mlp_surv2(
    const float* __restrict__ H, const int* __restrict__ mask,
    const float* __restrict__ nw1, const float* __restrict__ nb1,
    const float* __restrict__ nw2, const float* __restrict__ nb2,
    const float* __restrict__ mw1, const float* __restrict__ mb1,
    const float* __restrict__ mw2, const float* __restrict__ mb2,
    const float* __restrict__ dw1, const float* __restrict__ db1,
    const float* __restrict__ dw2, const float* __restrict__ db2,
    float* __restrict__ biasM)
{
    __shared__ float hs[8][256];
    __shared__ float red[24][128];

    int t = threadIdx.x;
    int tok0 = blockIdx.x * 8;

    #pragma unroll
    for (int i = 0; i < 16; i++) {
        int idx = t + i * 128; int tk = idx >> 8, c = idx & 255;
        hs[tk][c] = H[(size_t)(tok0 + tk) * 256 + c];
    }
    __syncthreads();

    const float* wn = nw1 + (size_t)t * 256;
    const float* wm = mw1 + (size_t)t * 256;
    const float* wd = dw1 + (size_t)t * 256;
    float sn[8], smu2[8], sd[8];
    #pragma unroll
    for (int k = 0; k < 8; k++) { sn[k] = 0.f; smu2[k] = 0.f; sd[k] = 0.f; }
    for (int i = 0; i < 256; i++) {
        float a = wn[i], bb = wm[i], c = wd[i];
        #pragma unroll
        for (int k = 0; k < 8; k++) {
            float hv = hs[k][i];
            sn[k] += a * hv; smu2[k] += bb * hv; sd[k] += c * hv;
        }
    }
    float a1 = nb1[t], a2 = nw2[t], b1 = mb1[t], b2 = mw2[t], c1 = db1[t], c2 = dw2[t];
    #pragma unroll
    for (int k = 0; k < 8; k++) {
        red[k][t]      = fmaxf(sn[k]   + a1, 0.f) * a2;
        red[8 + k][t]  = fmaxf(smu2[k] + b1, 0.f) * b2;
        red[16 + k][t] = fmaxf(sd[k]   + c1, 0.f) * c2;
    }
    __syncthreads();

    for (int s2 = 64; s2 > 0; s2 >>= 1) {
        for (int j = t; j < 24 * s2; j += 128) {
            int row = j / s2, c = j % s2;
            red[row][c] += red[row][c + s2];
        }
        __syncthreads();
    }

    if (t < 8) {
        float zn = red[t][0] + nb2[0];
        float zm = red[8 + t][0] + mb2[0];
        float zd = red[16 + t][0] + db2[0];
        float n     = (zn > 20.f) ? zn : log1pf(__expf(zn));
        float mu    = 1.f / (1.f + __expf(-zm));
        float delta = fmaxf(zd, 0.f);
        float surv  = logf(n + 1e-8f) + logf(mu + 1e-8f) - delta;
        biasM[tok0 + t] = 0.1f * surv + ((mask[tok0 + t] > 0) ? 0.f : -1e9f);
    }
}

// ---------------------------------------------------------------------------
// Launch
// ---------------------------------------------------------------------------
extern "C" void kernel_launch(void* const* d_in, const int* in_sizes, int n_in,
                              void* d_out, int out_size)
{
    const float* x        = (const float*)d_in[0];
    const int*   mask     = (const int*)  d_in[1];
    const float* qw = (const float*)d_in[2],  *qb = (const float*)d_in[3];
    const float* kw = (const float*)d_in[4],  *kb = (const float*)d_in[5];
    const float* vw = (const float*)d_in[6],  *vb = (const float*)d_in[7];
    const float* ow = (const float*)d_in[8],  *ob = (const float*)d_in[9];
    const float* sp_w = (const float*)d_in[10], *sp_b = (const float*)d_in[11];
    const float* sa_in_w  = (const float*)d_in[12], *sa_in_b  = (const float*)d_in[13];
    const float* sa_out_w = (const float*)d_in[14], *sa_out_b = (const float*)d_in[15];
    const float* nw1 = (const float*)d_in[16], *nb1 = (const float*)d_in[17];
    const float* nw2 = (const float*)d_in[18], *nb2 = (const float*)d_in[19];
    const float* mw1 = (const float*)d_in[20], *mb1 = (const float*)d_in[21];
    const float* mw2 = (const float*)d_in[22], *mb2 = (const float*)d_in[23];
    const float* dw1 = (const float*)d_in[24], *db1 = (const float*)d_in[25];
    const float* dw2 = (const float*)d_in[26], *db2 = (const float*)d_in[27];
    float* out = (float*)d_out;

    unsigned *xtf, *qwtf, *kwtf, *vwtf, *owtf, *spwtf, *saiwtf, *saowtf;
    unsigned *Q, *K, *V, *qkvs, *h0, *sattn, *attn, *VTm, *VTs;
    float *h1, *biasS, *biasM;
    cudaGetSymbolAddress((void**)&xtf,    g_xtf);
    cudaGetSymbolAddress((void**)&qwtf,   g_qwtf);
    cudaGetSymbolAddress((void**)&kwtf,   g_kwtf);
    cudaGetSymbolAddress((void**)&vwtf,   g_vwtf);
    cudaGetSymbolAddress((void**)&owtf,   g_owtf);
    cudaGetSymbolAddress((void**)&spwtf,  g_spwtf);
    cudaGetSymbolAddress((void**)&saiwtf, g_saiwtf);
    cudaGetSymbolAddress((void**)&saowtf, g_saowtf);
    cudaGetSymbolAddress((void**)&Q,      g_Q);
    cudaGetSymbolAddress((void**)&K,      g_K);
    cudaGetSymbolAddress((void**)&V,      g_V);
    cudaGetSymbolAddress((void**)&attn,   g_attn);
    cudaGetSymbolAddress((void**)&h0,     g_h0);
    cudaGetSymbolAddress((void**)&qkvs,   g_qkvs);
    cudaGetSymbolAddress((void**)&sattn,  g_sattn);
    cudaGetSymbolAddress((void**)&h1,     g_h1);
    cudaGetSymbolAddress((void**)&biasS,  g_biasS);
    cudaGetSymbolAddress((void**)&biasM,  g_biasM);
    cudaGetSymbolAddress((void**)&VTm,    g_VTm);
    cudaGetSymbolAddress((void**)&VTs,    g_VTs);

    const int M = MTOK, S = SEQ, B = BATCH, H = HDIM, I = IDIM;

    const int SM128 = 3 * (128 + 128) * 36 * 4;   // 110592
    const int SM64  = 3 * (64 + 128) * 36 * 4;    // 82944
    const int SMATT = (3 * 8704 + 128) * 4;       // 104960

    static cudaStream_t s1 = nullptr;
    static cudaEvent_t eFork = nullptr, eJoin = nullptr;
    static bool init_done = false, use_streams = false;
    if (!init_done) {
        use_streams =
            (cudaStreamCreateWithFlags(&s1, cudaStreamNonBlocking) == cudaSuccess) &&
            (cudaEventCreateWithFlags(&eFork, cudaEventDisableTiming) == cudaSuccess) &&
            (cudaEventCreateWithFlags(&eJoin, cudaEventDisableTiming) == cudaSuccess);
        cudaFuncSetAttribute((const void*)gemm_u<128, false>, cudaFuncAttributeMaxDynamicSharedMemorySize, SM128);
        cudaFuncSetAttribute((const void*)gemm_u<128, true>,  cudaFuncAttributeMaxDynamicSharedMemorySize, SM128);
        cudaFuncSetAttribute((const void*)gemm_u_qkv,         cudaFuncAttributeMaxDynamicSharedMemorySize, SM128);
        cudaFuncSetAttribute((const void*)gemm_u<64, false>,  cudaFuncAttributeMaxDynamicSharedMemorySize, SM64);
        cudaFuncSetAttribute((const void*)gemm_u<64, true>,   cudaFuncAttributeMaxDynamicSharedMemorySize, SM64);
        cudaFuncSetAttribute((const void*)attn8<false>,       cudaFuncAttributeMaxDynamicSharedMemorySize, SMATT);
        cudaFuncSetAttribute((const void*)attn8<true>,        cudaFuncAttributeMaxDynamicSharedMemorySize, SMATT);
        init_done = true;
    }

    // 0) convert x + all weights to tf32 bits; mask bias (seg 8)
    cvt_tf32_all<<<dim3(512, 9), 256>>>(x, qw, kw, vw, ow, sp_w, sa_in_w, sa_out_w, mask,
                                        xtf, qwtf, kwtf, vwtf, owtf, spwtf, saiwtf, saowtf,
                                        biasS);

    if (use_streams) {
        cudaEventRecord(eFork, 0);
        cudaStreamWaitEvent(s1, eFork, 0);
        gemm_u_qkv<<<dim3(H / 128, M / 128, 3), 256, SM128, s1>>>(
            xtf, qwtf, kwtf, vwtf, qb, kb, vb, Q, K, V, M, H, H);
        transpose_vt<<<dim3(S / 64, 12, B), 256, 0, s1>>>(V, VTm, S, H, 0, 12);
        cudaEventRecord(eJoin, s1);
    } else {
        gemm_u_qkv<<<dim3(H / 128, M / 128, 3), 256, SM128>>>(
            xtf, qwtf, kwtf, vwtf, qb, kb, vb, Q, K, V, M, H, H);
        transpose_vt<<<dim3(S / 64, 12, B), 256>>>(V, VTm, S, H, 0, 12);
    }

    // scorer chain (concurrent with QKV when streams work)
    gemm_u<64, true><<<dim3(I / 128, M / 64), 256, SM64>>>(xtf, spwtf, sp_b, h0, M, I, H);
    gemm_u<128, true><<<dim3(3 * I / 128, M / 128), 256, SM128>>>(h0, saiwtf, sa_in_b, qkvs, M, 3 * I, I);
    transpose_vt<<<dim3(S / 64, 4, B), 256>>>(qkvs, VTs, S, 3 * I, 2 * I, 4);
    attn8<true><<<dim3(S / 128, 4, B), 256, SMATT>>>(qkvs, qkvs, VTs, biasS, sattn,
                                                     S, 3 * I, 0, I, 4, I, 0);
    gemm_u<64, false><<<dim3(I / 128, M / 64), 256, SM64>>>(sattn, saowtf, sa_out_b, h1, M, I, I);
    mlp_surv2<<<M / 8, 128>>>(h1, mask, nw1, nb1, nw2, nb2,
                              mw1, mb1, mw2, mb2, dw1, db1, dw2, db2, biasM);

    // join, then main attention + output projection
    if (use_streams) cudaStreamWaitEvent(0, eJoin, 0);
    attn8<true><<<dim3(S / 128, 12, B), 256, SMATT>>>(Q, K, VTm, biasM, attn,
                                                      S, H, 0, 0, 12, H, 0);
    gemm_u<128, false><<<dim3(H / 128, M / 128), 256, SM128>>>(attn, owtf, ob, out, M, H, H);
}

// round 16
// speedup vs baseline: 1.0535x; 1.0535x over previous
#include <cuda_runtime.h>
#include <cuda_bf16.h>
#include <cstdint>

#define BATCH 2
#define SEQ   2048
#define HDIM  768
#define IDIM  256
#define MTOK  (BATCH * SEQ)   // 4096 tokens

// ---------------------------------------------------------------------------
// Scratch (device globals; no allocation allowed)
// ---------------------------------------------------------------------------
__device__ unsigned g_xtf [MTOK * HDIM];
__device__ unsigned g_qwtf[HDIM * HDIM];
__device__ unsigned g_kwtf[HDIM * HDIM];
__device__ unsigned g_vwtf[HDIM * HDIM];
__device__ unsigned g_owtf[HDIM * HDIM];
__device__ unsigned g_spwtf [IDIM * HDIM];
__device__ unsigned g_saiwtf[3 * IDIM * IDIM];
__device__ unsigned g_saowtf[IDIM * IDIM];

__device__ unsigned g_Q[MTOK * HDIM];
__device__ unsigned g_K[MTOK * HDIM];
__device__ unsigned g_V[MTOK * HDIM];
__device__ unsigned g_attn[MTOK * HDIM];
__device__ unsigned g_h0[MTOK * IDIM];
__device__ unsigned g_qkvs[MTOK * 3 * IDIM];
__device__ unsigned g_sattn[MTOK * IDIM];
__device__ float    g_h1[MTOK * IDIM];
__device__ float    g_biasS[MTOK];
__device__ float    g_biasM[MTOK];

// transposed V: VT[b][h][d][S] (tf32 bits)
__device__ unsigned g_VTm[BATCH * 12 * 64 * SEQ];
__device__ unsigned g_VTs[BATCH * 4 * 64 * SEQ];

// ---------------------------------------------------------------------------
// Helpers
// ---------------------------------------------------------------------------
__device__ __forceinline__ unsigned f2tf(float f) {
    unsigned r; asm("cvt.rna.tf32.f32 %0, %1;" : "=r"(r) : "f"(f)); return r;
}
__device__ __forceinline__ float ex2(float x) {
    float r; asm("ex2.approx.f32 %0, %1;" : "=f"(r) : "f"(x)); return r;
}
__device__ __forceinline__ void mma8(float c[4], const unsigned a[4], const unsigned b[2]) {
    asm volatile(
        "mma.sync.aligned.m16n8k8.row.col.f32.tf32.tf32.f32 "
        "{%0,%1,%2,%3},{%4,%5,%6,%7},{%8,%9},{%0,%1,%2,%3};"
        : "+f"(c[0]), "+f"(c[1]), "+f"(c[2]), "+f"(c[3])
        : "r"(a[0]), "r"(a[1]), "r"(a[2]), "r"(a[3]), "r"(b[0]), "r"(b[1]));
}
__device__ __forceinline__ void ldmx4(unsigned& r0, unsigned& r1, unsigned& r2, unsigned& r3,
                                      unsigned addr) {
    asm volatile("ldmatrix.sync.aligned.m8n8.x4.shared.b16 {%0,%1,%2,%3}, [%4];"
                 : "=r"(r0), "=r"(r1), "=r"(r2), "=r"(r3) : "r"(addr));
}
__device__ __forceinline__ unsigned s2u(const void* p) {
    return (unsigned)__cvta_generic_to_shared(p);
}
__device__ __forceinline__ void cp16(unsigned dst, const void* src) {
    asm volatile("cp.async.ca.shared.global [%0], [%1], 16;" :: "r"(dst), "l"(src));
}
__device__ __forceinline__ void cp_commit() { asm volatile("cp.async.commit_group;"); }
__device__ __forceinline__ void cp_wait0() { asm volatile("cp.async.wait_group 0;"); }
__device__ __forceinline__ void cp_wait1() { asm volatile("cp.async.wait_group 1;"); }

// ---------------------------------------------------------------------------
// One-shot tf32 conversion of x + all GEMM weights + mask bias (9 segments)
// ---------------------------------------------------------------------------
__global__ __launch_bounds__(256) void cvt_tf32_all(
    const float* __restrict__ x,   const float* __restrict__ qw,
    const float* __restrict__ kw,  const float* __restrict__ vw,
    const float* __restrict__ ow,  const float* __restrict__ spw,
    const float* __restrict__ saiw,const float* __restrict__ saow,
    const int* __restrict__ mask,
    unsigned* __restrict__ xo,  unsigned* __restrict__ qo,
    unsigned* __restrict__ ko,  unsigned* __restrict__ vo,
    unsigned* __restrict__ oo,  unsigned* __restrict__ spo,
    unsigned* __restrict__ saio,unsigned* __restrict__ saoo,
    float* __restrict__ biasS)
{
    const int seg = blockIdx.y;
    if (seg == 8) {
        for (int i = blockIdx.x * 256 + threadIdx.x; i < MTOK; i += gridDim.x * 256)
            biasS[i] = (mask[i] > 0) ? 0.f : -1e9f;
        return;
    }
    int n;
    const float* s; unsigned* d;
    switch (seg) {
        case 0: s = x;    d = xo;   n = MTOK * HDIM;     break;
        case 1: s = qw;   d = qo;   n = HDIM * HDIM;     break;
        case 2: s = kw;   d = ko;   n = HDIM * HDIM;     break;
        case 3: s = vw;   d = vo;   n = HDIM * HDIM;     break;
        case 4: s = ow;   d = oo;   n = HDIM * HDIM;     break;
        case 5: s = spw;  d = spo;  n = IDIM * HDIM;     break;
        case 6: s = saiw; d = saio; n = 3 * IDIM * IDIM; break;
        default:s = saow; d = saoo; n = IDIM * IDIM;     break;
    }
    int n4 = n >> 2;
    for (int i = blockIdx.x * 256 + threadIdx.x; i < n4; i += gridDim.x * 256) {
        float4 v = ((const float4*)s)[i];
        ((uint4*)d)[i] = make_uint4(f2tf(v.x), f2tf(v.y), f2tf(v.z), f2tf(v.w));
    }
}

// ---------------------------------------------------------------------------
// V transpose: V[(b*S+key)*ld + v_off + h*64 + d] -> VT[((b*nh+h)*64+d)*S + key]
// ---------------------------------------------------------------------------
__global__ __launch_bounds__(256) void transpose_vt(
    const unsigned* __restrict__ V, unsigned* __restrict__ VT,
    int S, int ld, int v_off, int nh)
{
    __shared__ unsigned tsm[64 * 68];
    int b = blockIdx.z, h = blockIdx.y, k0 = blockIdx.x * 64;
    int tid = threadIdx.x;
    const unsigned* src = V + v_off + h * 64;

    #pragma unroll
    for (int i = 0; i < 4; i++) {
        int idx = tid + i * 256;
        int key = idx >> 4, d4 = (idx & 15) * 4;
        uint4 v = *(const uint4*)(src + (size_t)(b * S + k0 + key) * ld + d4);
        *(uint4*)&tsm[key * 68 + d4] = v;
    }
    __syncthreads();
    #pragma unroll
    for (int i = 0; i < 4; i++) {
        int idx = tid + i * 256;
        int d = idx >> 4, kk = (idx & 15) * 4;
        uint4 w = make_uint4(tsm[(kk + 0) * 68 + d], tsm[(kk + 1) * 68 + d],
                             tsm[(kk + 2) * 68 + d], tsm[(kk + 3) * 68 + d]);
        *(uint4*)(VT + ((size_t)(b * nh + h) * 64 + d) * S + k0 + kk) = w;
    }
}

// ---------------------------------------------------------------------------
// GEMM (tf32-bit inputs), BM x 128 tile, BK=32, cp.async 2-stage (R14-proven),
// ldmatrix fragment loads (proven mapping from attention).
// ---------------------------------------------------------------------------
template<int BM, bool TF32OUT>
__device__ __forceinline__ void gemm_body(
    const unsigned* __restrict__ A, const unsigned* __restrict__ W,
    const float* __restrict__ bias, void* __restrict__ Cv,
    int M, int N, int K, unsigned* smemu)
{
    constexpr int MFRAG = BM / 32;
    unsigned* As = smemu;
    unsigned* Bs = smemu + 2 * BM * 36;

    int tid = threadIdx.x, warp = tid >> 5, lane = tid & 31, g = lane >> 2, tig = lane & 3;
    int wm = (warp & 1) * (BM / 2), wn = (warp >> 1) * 32;
    int bm = blockIdx.y * BM, bn = blockIdx.x * 128;

    float acc[MFRAG][4][4];
    #pragma unroll
    for (int mt = 0; mt < MFRAG; mt++)
        #pragma unroll
        for (int nt = 0; nt < 4; nt++)
            #pragma unroll
            for (int i = 0; i < 4; i++) acc[mt][nt][i] = 0.f;

    auto issue = [&](int stage, int k0) {
        #pragma unroll
        for (int i = 0; i < BM / 32; i++) {
            int idx = tid + i * 256;
            int r = idx >> 3, c4 = (idx & 7) * 4;
            cp16(s2u(&As[stage * BM * 36 + r * 36 + c4]),
                 A + (size_t)(bm + r) * K + k0 + c4);
        }
        #pragma unroll
        for (int i = 0; i < 4; i++) {
            int idx = tid + i * 256;
            int r = idx >> 3, c4 = (idx & 7) * 4;
            cp16(s2u(&Bs[stage * 128 * 36 + r * 36 + c4]),
                 W + (size_t)(bn + r) * K + k0 + c4);
        }
        cp_commit();
    };

    // ldmatrix lane offsets (u32 units, row stride 36)
    int lr8 = lane & 7, sel = lane >> 3;
    int aoff = lr8 * 36 + ((sel & 1) ? 8 * 36 : 0) + ((sel >> 1) ? 4 : 0);  // A-frag
    int boff = lr8 * 36 + ((sel & 1) ? 4 : 0) + ((sel >> 1) ? 8 * 36 : 0);  // B-frag

    int ntiles = K / 32;
    issue(0, 0);
    for (int t = 0; t < ntiles; t++) {
        if (t + 1 < ntiles) { issue((t + 1) & 1, (t + 1) * 32); cp_wait1(); }
        else                { cp_wait0(); }
        __syncthreads();

        const unsigned* as = As + (t & 1) * BM * 36;
        const unsigned* bs = Bs + (t & 1) * 128 * 36;
        #pragma unroll
        for (int ks = 0; ks < 4; ks++) {
            unsigned af[MFRAG][4], bf[4][2];
            #pragma unroll
            for (int mt = 0; mt < MFRAG; mt++) {
                unsigned addr = s2u(&as[(wm + mt * 16) * 36 + ks * 8 + aoff]);
                ldmx4(af[mt][0], af[mt][1], af[mt][2], af[mt][3], addr);
            }
            #pragma unroll
            for (int ntp = 0; ntp < 2; ntp++) {
                unsigned addr = s2u(&bs[(wn + ntp * 16) * 36 + ks * 8 + boff]);
                ldmx4(bf[2 * ntp][0], bf[2 * ntp][1],
                      bf[2 * ntp + 1][0], bf[2 * ntp + 1][1], addr);
            }
            #pragma unroll
            for (int mt = 0; mt < MFRAG; mt++)
                #pragma unroll
                for (int nt = 0; nt < 4; nt++)
                    mma8(acc[mt][nt], af[mt], bf[nt]);
        }
        __syncthreads();
    }

    #pragma unroll
    for (int mt = 0; mt < MFRAG; mt++) {
        int row0 = bm + wm + mt * 16 + g;
        #pragma unroll
        for (int nt = 0; nt < 4; nt++) {
            int col = bn + wn + nt * 8 + 2 * tig;
            float b0 = __ldg(bias + col), b1 = __ldg(bias + col + 1);
            float v00 = acc[mt][nt][0] + b0, v01 = acc[mt][nt][1] + b1;
            float v10 = acc[mt][nt][2] + b0, v11 = acc[mt][nt][3] + b1;
            if (TF32OUT) {
                unsigned* Cu = (unsigned*)Cv;
                *(uint2*)(Cu + (size_t)row0 * N + col) = make_uint2(f2tf(v00), f2tf(v01));
                *(uint2*)(Cu + (size_t)(row0 + 8) * N + col) = make_uint2(f2tf(v10), f2tf(v11));
            } else {
                float* C = (float*)Cv;
                *(float2*)(C + (size_t)row0 * N + col) = make_float2(v00, v01);
                *(float2*)(C + (size_t)(row0 + 8) * N + col) = make_float2(v10, v11);
            }
        }
    }
}

template<int BM, bool TF32OUT>
__global__ __launch_bounds__(256, 2) void gemm_u(
    const unsigned* __restrict__ A, const unsigned* __restrict__ W,
    const float* __restrict__ bias, void* __restrict__ C,
    int M, int N, int K)
{
    extern __shared__ unsigned smemu[];
    gemm_body<BM, TF32OUT>(A, W, bias, C, M, N, K, smemu);
}

__global__ __launch_bounds__(256, 2) void gemm_u_qkv(
    const unsigned* __restrict__ A,
    const unsigned* __restrict__ w0, const unsigned* __restrict__ w1, const unsigned* __restrict__ w2,
    const float* __restrict__ b0, const float* __restrict__ b1, const float* __restrict__ b2,
    unsigned* __restrict__ c0, unsigned* __restrict__ c1, unsigned* __restrict__ c2,
    int M, int N, int K)
{
    extern __shared__ unsigned smemu[];
    int z = blockIdx.z;
    const unsigned* W = (z == 0) ? w0 : (z == 1) ? w1 : w2;
    const float* bias = (z == 0) ? b0 : (z == 1) ? b1 : b2;
    unsigned* C = (z == 0) ? c0 : (z == 1) ? c1 : c2;
    gemm_body<128, true>(A, W, bias, C, M, N, K, smemu);
}

// ---------------------------------------------------------------------------
// Flash attention v8 (proven R14): tf32-bit Q/K + transposed V (VT[d][S]).
// ldmatrix fragment loads for K (QK), P and VT (PV). 256 thr / 128 queries.
// ---------------------------------------------------------------------------
template<bool TF32OUT>
__global__ __launch_bounds__(256, 2) void attn8(
    const unsigned* __restrict__ Qp, const unsigned* __restrict__ Kp,
    const unsigned* __restrict__ VT, const float* __restrict__ bias,
    void* __restrict__ Opv,
    int S, int ld, int q_off, int k_off, int nh, int o_ld, int o_off)
{
    extern __shared__ unsigned smu[];
    unsigned* KVs = smu;                       // [2][8704]: K rows 0-63, VT rows 64-127
    unsigned* Ps  = smu + 2 * 8704;            // [8704]
    float* bsL    = (float*)(smu + 3 * 8704);  // [2][64]

    const float LOG2E = 1.4426950408889634f;
    int b = blockIdx.z, h = blockIdx.y, q0 = blockIdx.x * 128;
    int tid = threadIdx.x, warp = tid >> 5, lane = tid & 31, g = lane >> 2, tig = lane & 3;

    const unsigned* qbase = Qp + q_off + h * 64;
    const unsigned* kbase = Kp + k_off + h * 64;
    const unsigned* vtb   = VT + (size_t)(b * nh + h) * 64 * S;

    // ---- stage Q (128x64 tf32) via cp.async ----
    #pragma unroll
    for (int i = 0; i < 8; i++) {
        int idx = tid + i * 256; int r = idx >> 4, s = (idx & 15) * 4;
        cp16(s2u(&Ps[r * 68 + s]), qbase + (size_t)(b * S + q0 + r) * ld + s);
    }
    cp_commit();

    auto issue = [&](int st, int kt) {
        #pragma unroll
        for (int i = 0; i < 4; i++) {
            int idx = tid + i * 256;
            int r = idx >> 4, c = (idx & 15) * 4;
            cp16(s2u(&KVs[st * 8704 + r * 68 + c]),
                 kbase + (size_t)(b * S + kt + r) * ld + c);
            cp16(s2u(&KVs[st * 8704 + (64 + r) * 68 + c]),
                 vtb + (size_t)r * S + kt + c);
        }
        if (tid < 16)
            cp16(s2u(&bsL[st * 64 + tid * 4]), bias + (size_t)b * S + kt + tid * 4);
        cp_commit();
    };

    issue(0, 0);
    cp_wait1();           // Q group retired
    __syncthreads();

    unsigned qf[8][4];
    int qr = warp * 16;
    #pragma unroll
    for (int ks = 0; ks < 8; ks++) {
        qf[ks][0] = Ps[(qr + g) * 68 + ks * 8 + tig];
        qf[ks][1] = Ps[(qr + g + 8) * 68 + ks * 8 + tig];
        qf[ks][2] = Ps[(qr + g) * 68 + ks * 8 + tig + 4];
        qf[ks][3] = Ps[(qr + g + 8) * 68 + ks * 8 + tig + 4];
    }

    float o[8][4];
    #pragma unroll
    for (int nt = 0; nt < 8; nt++)
        #pragma unroll
        for (int i = 0; i < 4; i++) o[nt][i] = 0.f;
    float m0 = -1e30f, m1 = -1e30f, l0 = 0.f, l1 = 0.f;
    const float sc = 0.125f * LOG2E;
    unsigned* pw = Ps + warp * 16 * 68;

    int lr8 = lane & 7, sel = lane >> 3;
    int koff = lr8 * 68 + ((sel & 1) ? 4 : 0) + ((sel >> 1) ? 8 * 68 : 0);
    int poff = lr8 * 68 + ((sel & 1) ? 8 * 68 : 0) + ((sel >> 1) ? 4 : 0);

    int ntile = S / 64;
    for (int t = 0; t < ntile; t++) {
        int st = t & 1;
        if (t + 1 < ntile) { issue(st ^ 1, (t + 1) * 64); cp_wait1(); }
        else               { cp_wait0(); }
        __syncthreads();

        const unsigned* KVf = KVs + st * 8704;
        const float* bsf = bsL + st * 64;

        // ---- S = Q K^T (ldmatrix K fragments) ----
        float sa[8][4];
        #pragma unroll
        for (int nt = 0; nt < 8; nt++)
            #pragma unroll
            for (int i = 0; i < 4; i++) sa[nt][i] = 0.f;
        #pragma unroll
        for (int ks = 0; ks < 8; ks++) {
            unsigned bf[8][2];
            #pragma unroll
            for (int ntp = 0; ntp < 4; ntp++) {
                unsigned addr = s2u(&KVf[ntp * 16 * 68 + ks * 8 + koff]);
                ldmx4(bf[2 * ntp][0], bf[2 * ntp][1],
                      bf[2 * ntp + 1][0], bf[2 * ntp + 1][1], addr);
            }
            #pragma unroll
            for (int nt = 0; nt < 8; nt++) mma8(sa[nt], qf[ks], bf[nt]);
        }

        // ---- online softmax (exp2 domain) ----
        float rm0 = -1e30f, rm1 = -1e30f;
        #pragma unroll
        for (int nt = 0; nt < 8; nt++) {
            float bl0 = bsf[nt * 8 + 2 * tig] * LOG2E;
            float bl1 = bsf[nt * 8 + 2 * tig + 1] * LOG2E;
            sa[nt][0] = sa[nt][0] * sc + bl0;
            sa[nt][1] = sa[nt][1] * sc + bl1;
            sa[nt][2] = sa[nt][2] * sc + bl0;
            sa[nt][3] = sa[nt][3] * sc + bl1;
            rm0 = fmaxf(rm0, fmaxf(sa[nt][0], sa[nt][1]));
            rm1 = fmaxf(rm1, fmaxf(sa[nt][2], sa[nt][3]));
        }
        rm0 = fmaxf(rm0, __shfl_xor_sync(0xffffffffu, rm0, 1));
        rm0 = fmaxf(rm0, __shfl_xor_sync(0xffffffffu, rm0, 2));
        rm1 = fmaxf(rm1, __shfl_xor_sync(0xffffffffu, rm1, 1));
        rm1 = fmaxf(rm1, __shfl_xor_sync(0xffffffffu, rm1, 2));
        float mn0 = fmaxf(m0, rm0), mn1 = fmaxf(m1, rm1);
        float c0 = ex2(m0 - mn0), c1 = ex2(m1 - mn1);
        float rs0 = 0.f, rs1 = 0.f;
        #pragma unroll
        for (int nt = 0; nt < 8; nt++) {
            sa[nt][0] = ex2(sa[nt][0] - mn0);
            sa[nt][1] = ex2(sa[nt][1] - mn0);
            sa[nt][2] = ex2(sa[nt][2] - mn1);
            sa[nt][3] = ex2(sa[nt][3] - mn1);
            rs0 += sa[nt][0] + sa[nt][1];
            rs1 += sa[nt][2] + sa[nt][3];
        }
        rs0 += __shfl_xor_sync(0xffffffffu, rs0, 1);
        rs0 += __shfl_xor_sync(0xffffffffu, rs0, 2);
        rs1 += __shfl_xor_sync(0xffffffffu, rs1, 1);
        rs1 += __shfl_xor_sync(0xffffffffu, rs1, 2);
        l0 = l0 * c0 + rs0; l1 = l1 * c1 + rs1;
        m0 = mn0; m1 = mn1;
        #pragma unroll
        for (int nt = 0; nt < 8; nt++) {
            o[nt][0] *= c0; o[nt][1] *= c0; o[nt][2] *= c1; o[nt][3] *= c1;
        }

        // ---- P -> warp-private smem (tf32) ----
        #pragma unroll
        for (int nt = 0; nt < 8; nt++) {
            int cc = nt * 8 + 2 * tig;
            pw[g * 68 + cc]           = f2tf(sa[nt][0]);
            pw[g * 68 + cc + 1]       = f2tf(sa[nt][1]);
            pw[(g + 8) * 68 + cc]     = f2tf(sa[nt][2]);
            pw[(g + 8) * 68 + cc + 1] = f2tf(sa[nt][3]);
        }
        __syncwarp();

        // ---- O += P V (ldmatrix P + ldmatrix VT fragments) ----
        #pragma unroll
        for (int ks = 0; ks < 8; ks++) {
            unsigned af[4];
            {
                unsigned addr = s2u(&pw[ks * 8 + poff]);
                ldmx4(af[0], af[1], af[2], af[3], addr);
            }
            unsigned bf2[8][2];
            #pragma unroll
            for (int ntp = 0; ntp < 4; ntp++) {
                unsigned addr = s2u(&KVf[64 * 68 + ntp * 16 * 68 + ks * 8 + koff]);
                ldmx4(bf2[2 * ntp][0], bf2[2 * ntp][1],
                      bf2[2 * ntp + 1][0], bf2[2 * ntp + 1][1], addr);
            }
            #pragma unroll
            for (int nt = 0; nt < 8; nt++) mma8(o[nt], af, bf2[nt]);
        }
        __syncthreads();
    }

    // ---- normalize + write ----
    float inv0 = 1.f / l0, inv1 = 1.f / l1;
    int row0 = b * S + q0 + warp * 16 + g;
    if (TF32OUT) {
        unsigned* ou0 = (unsigned*)Opv + o_off + h * 64 + (size_t)row0 * o_ld;
        unsigned* ou1 = (unsigned*)Opv + o_off + h * 64 + (size_t)(row0 + 8) * o_ld;
        #pragma unroll
        for (int nt = 0; nt < 8; nt++) {
            int col = nt * 8 + 2 * tig;
            *(uint2*)(ou0 + col) = make_uint2(f2tf(o[nt][0] * inv0), f2tf(o[nt][1] * inv0));
            *(uint2*)(ou1 + col) = make_uint2(f2tf(o[nt][2] * inv1), f2tf(o[nt][3] * inv1));
        }
    } else {
        float* ob0 = (float*)Opv + o_off + h * 64 + (size_t)row0 * o_ld;
        float* ob1 = (float*)Opv + o_off + h * 64 + (size_t)(row0 + 8) * o_ld;
        #pragma unroll
        for (int nt = 0; nt < 8; nt++) {
            int col = nt * 8 + 2 * tig;
            *(float2*)(ob0 + col) = make_float2(o[nt][0] * inv0, o[nt][1] * inv0);
            *(float2*)(ob1 + col) = make_float2(o[nt][2] * inv1, o[nt][3] * inv1);
        }
    }
}

// ---------------------------------------------------------------------------
// Fused survival MLPs, 8 tokens per block
// ---------------------------------------------------------------------------
__global__ __launch_bounds__(128) void mlp_surv2(
    const float* __restrict__ H, const int* __restrict__ mask,
    const float* __restrict__ nw1, const float* __restrict__ nb1,
    const float* __restrict__ nw2, const float* __restrict__ nb2,
    const float* __restrict__ mw1, const float* __restrict__ mb1,
    const float* __restrict__ mw2, const float* __restrict__ mb2,
    const float* __restrict__ dw1, const float* __restrict__ db1,
    const float* __restrict__ dw2, const float* __restrict__ db2,
    float* __restrict__ biasM)
{
    __shared__ float hs[8][256];
    __shared__ float red[24][128];

    int t = threadIdx.x;
    int tok0 = blockIdx.x * 8;

    #pragma unroll
    for (int i = 0; i < 16; i++) {
        int idx = t + i * 128; int tk = idx >> 8, c = idx & 255;
        hs[tk][c] = H[(size_t)(tok0 + tk) * 256 + c];
    }
    __syncthreads();

    const float* wn = nw1 + (size_t)t * 256;
    const float* wm = mw1 + (size_t)t * 256;
    const float* wd = dw1 + (size_t)t * 256;
    float sn[8], smu2[8], sd[8];
    #pragma unroll
    for (int k = 0; k < 8; k++) { sn[k] = 0.f; smu2[k] = 0.f; sd[k] = 0.f; }
    for (int i = 0; i < 256; i++) {
        float a = wn[i], bb = wm[i], c = wd[i];
        #pragma unroll
        for (int k = 0; k < 8; k++) {
            float hv = hs[k][i];
            sn[k] += a * hv; smu2[k] += bb * hv; sd[k] += c * hv;
        }
    }
    float a1 = nb1[t], a2 = nw2[t], b1 = mb1[t], b2 = mw2[t], c1 = db1[t], c2 = dw2[t];
    #pragma unroll
    for (int k = 0; k < 8; k++) {
        red[k][t]      = fmaxf(sn[k]   + a1, 0.f) * a2;
        red[8 + k][t]  = fmaxf(smu2[k] + b1, 0.f) * b2;
        red[16 + k][t] = fmaxf(sd[k]   + c1, 0.f) * c2;
    }
    __syncthreads();

    for (int s2 = 64; s2 > 0; s2 >>= 1) {
        for (int j = t; j < 24 * s2; j += 128) {
            int row = j / s2, c = j % s2;
            red[row][c] += red[row][c + s2];
        }
        __syncthreads();
    }

    if (t < 8) {
        float zn = red[t][0] + nb2[0];
        float zm = red[8 + t][0] + mb2[0];
        float zd = red[16 + t][0] + db2[0];
        float n     = (zn > 20.f) ? zn : log1pf(__expf(zn));
        float mu    = 1.f / (1.f + __expf(-zm));
        float delta = fmaxf(zd, 0.f);
        float surv  = logf(n + 1e-8f) + logf(mu + 1e-8f) - delta;
        biasM[tok0 + t] = 0.1f * surv + ((mask[tok0 + t] > 0) ? 0.f : -1e9f);
    }
}

// ---------------------------------------------------------------------------
// Launch
// ---------------------------------------------------------------------------
extern "C" void kernel_launch(void* const* d_in, const int* in_sizes, int n_in,
                              void* d_out, int out_size)
{
    const float* x        = (const float*)d_in[0];
    const int*   mask     = (const int*)  d_in[1];
    const float* qw = (const float*)d_in[2],  *qb = (const float*)d_in[3];
    const float* kw = (const float*)d_in[4],  *kb = (const float*)d_in[5];
    const float* vw = (const float*)d_in[6],  *vb = (const float*)d_in[7];
    const float* ow = (const float*)d_in[8],  *ob = (const float*)d_in[9];
    const float* sp_w = (const float*)d_in[10], *sp_b = (const float*)d_in[11];
    const float* sa_in_w  = (const float*)d_in[12], *sa_in_b  = (const float*)d_in[13];
    const float* sa_out_w = (const float*)d_in[14], *sa_out_b = (const float*)d_in[15];
    const float* nw1 = (const float*)d_in[16], *nb1 = (const float*)d_in[17];
    const float* nw2 = (const float*)d_in[18], *nb2 = (const float*)d_in[19];
    const float* mw1 = (const float*)d_in[20], *mb1 = (const float*)d_in[21];
    const float* mw2 = (const float*)d_in[22], *mb2 = (const float*)d_in[23];
    const float* dw1 = (const float*)d_in[24], *db1 = (const float*)d_in[25];
    const float* dw2 = (const float*)d_in[26], *db2 = (const float*)d_in[27];
    float* out = (float*)d_out;

    unsigned *xtf, *qwtf, *kwtf, *vwtf, *owtf, *spwtf, *saiwtf, *saowtf;
    unsigned *Q, *K, *V, *qkvs, *h0, *sattn, *attn, *VTm, *VTs;
    float *h1, *biasS, *biasM;
    cudaGetSymbolAddress((void**)&xtf,    g_xtf);
    cudaGetSymbolAddress((void**)&qwtf,   g_qwtf);
    cudaGetSymbolAddress((void**)&kwtf,   g_kwtf);
    cudaGetSymbolAddress((void**)&vwtf,   g_vwtf);
    cudaGetSymbolAddress((void**)&owtf,   g_owtf);
    cudaGetSymbolAddress((void**)&spwtf,  g_spwtf);
    cudaGetSymbolAddress((void**)&saiwtf, g_saiwtf);
    cudaGetSymbolAddress((void**)&saowtf, g_saowtf);
    cudaGetSymbolAddress((void**)&Q,      g_Q);
    cudaGetSymbolAddress((void**)&K,      g_K);
    cudaGetSymbolAddress((void**)&V,      g_V);
    cudaGetSymbolAddress((void**)&attn,   g_attn);
    cudaGetSymbolAddress((void**)&h0,     g_h0);
    cudaGetSymbolAddress((void**)&qkvs,   g_qkvs);
    cudaGetSymbolAddress((void**)&sattn,  g_sattn);
    cudaGetSymbolAddress((void**)&h1,     g_h1);
    cudaGetSymbolAddress((void**)&biasS,  g_biasS);
    cudaGetSymbolAddress((void**)&biasM,  g_biasM);
    cudaGetSymbolAddress((void**)&VTm,    g_VTm);
    cudaGetSymbolAddress((void**)&VTs,    g_VTs);

    const int M = MTOK, S = SEQ, B = BATCH, H = HDIM, I = IDIM;

    const int SM128 = (2 * 128 * 36 + 2 * 128 * 36) * 4;   // 73728
    const int SM64  = (2 * 64 * 36 + 2 * 128 * 36) * 4;    // 55296
    const int SMATT = (3 * 8704 + 128) * 4;                // 104960

    static cudaStream_t s1 = nullptr;
    static cudaEvent_t eFork = nullptr, eJoin = nullptr;
    static bool init_done = false, use_streams = false;
    if (!init_done) {
        use_streams =
            (cudaStreamCreateWithFlags(&s1, cudaStreamNonBlocking) == cudaSuccess) &&
            (cudaEventCreateWithFlags(&eFork, cudaEventDisableTiming) == cudaSuccess) &&
            (cudaEventCreateWithFlags(&eJoin, cudaEventDisableTiming) == cudaSuccess);
        cudaFuncSetAttribute((const void*)gemm_u<128, false>, cudaFuncAttributeMaxDynamicSharedMemorySize, SM128);
        cudaFuncSetAttribute((const void*)gemm_u<128, true>,  cudaFuncAttributeMaxDynamicSharedMemorySize, SM128);
        cudaFuncSetAttribute((const void*)gemm_u_qkv,         cudaFuncAttributeMaxDynamicSharedMemorySize, SM128);
        cudaFuncSetAttribute((const void*)gemm_u<64, false>,  cudaFuncAttributeMaxDynamicSharedMemorySize, SM64);
        cudaFuncSetAttribute((const void*)gemm_u<64, true>,   cudaFuncAttributeMaxDynamicSharedMemorySize, SM64);
        cudaFuncSetAttribute((const void*)attn8<false>,       cudaFuncAttributeMaxDynamicSharedMemorySize, SMATT);
        cudaFuncSetAttribute((const void*)attn8<true>,        cudaFuncAttributeMaxDynamicSharedMemorySize, SMATT);
        init_done = true;
    }

    // 0) convert x + all weights to tf32 bits; mask bias (seg 8)
    cvt_tf32_all<<<dim3(512, 9), 256>>>(x, qw, kw, vw, ow, sp_w, sa_in_w, sa_out_w, mask,
                                        xtf, qwtf, kwtf, vwtf, owtf, spwtf, saiwtf, saowtf,
                                        biasS);

    if (use_streams) {
        cudaEventRecord(eFork, 0);
        cudaStreamWaitEvent(s1, eFork, 0);
        gemm_u_qkv<<<dim3(H / 128, M / 128, 3), 256, SM128, s1>>>(
            xtf, qwtf, kwtf, vwtf, qb, kb, vb, Q, K, V, M, H, H);
        transpose_vt<<<dim3(S / 64, 12, B), 256, 0, s1>>>(V, VTm, S, H, 0, 12);
        cudaEventRecord(eJoin, s1);
    } else {
        gemm_u_qkv<<<dim3(H / 128, M / 128, 3), 256, SM128>>>(
            xtf, qwtf, kwtf, vwtf, qb, kb, vb, Q, K, V, M, H, H);
        transpose_vt<<<dim3(S / 64, 12, B), 256>>>(V, VTm, S, H, 0, 12);
    }

    // scorer chain (concurrent with QKV when streams work)
    gemm_u<64, true><<<dim3(I / 128, M / 64), 256, SM64>>>(xtf, spwtf, sp_b, h0, M, I, H);
    gemm_u<128, true><<<dim3(3 * I / 128, M / 128), 256, SM128>>>(h0, saiwtf, sa_in_b, qkvs, M, 3 * I, I);
    transpose_vt<<<dim3(S / 64, 4, B), 256>>>(qkvs, VTs, S, 3 * I, 2 * I, 4);
    attn8<true><<<dim3(S / 128, 4, B), 256, SMATT>>>(qkvs, qkvs, VTs, biasS, sattn,
                                                     S, 3 * I, 0, I, 4, I, 0);
    gemm_u<64, false><<<dim3(I / 128, M / 64), 256, SM64>>>(sattn, saowtf, sa_out_b, h1, M, I, I);
    mlp_surv2<<<M / 8, 128>>>(h1, mask, nw1, nb1, nw2, nb2,
                              mw1, mb1, mw2, mb2, dw1, db1, dw2, db2, biasM);

    // join, then main attention + output projection
    if (use_streams) cudaStreamWaitEvent(0, eJoin, 0);
    attn8<true><<<dim3(S / 128, 12, B), 256, SMATT>>>(Q, K, VTm, biasM, attn,
                                                      S, H, 0, 0, 12, H, 0);
    gemm_u<128, false><<<dim3(H / 128, M / 128), 256, SM128>>>(attn, owtf, ob, out, M, H, H);
}